// round 15
// baseline (speedup 1.0000x reference)
#include <cuda_runtime.h>
#include <cstdint>

#define Bn  64
#define Hn  256
#define LCn 2048
#define LQn 256
#define NEGV (-1e30f)
#define NINF __int_as_float(0xff800000)

// ---------------- scratch ----------------
__device__ float g_S [(size_t)Bn * LCn * LQn];
__device__ float g_Qt[(size_t)Bn * LQn * Hn];   // tf32 bits (pre-rounded)
__device__ float g_T [(size_t)Bn * LQn * Hn];   // tf32 bits (pre-rounded)

// ---------------- helpers ----------------
__device__ __forceinline__ unsigned f2tf(float x) {
    unsigned r; asm("cvt.rna.tf32.f32 %0, %1;" : "=r"(r) : "f"(x)); return r;
}
__device__ __forceinline__ void mma8(float* d, const unsigned* a, unsigned b0, unsigned b1) {
    asm("mma.sync.aligned.m16n8k8.row.col.f32.tf32.tf32.f32 "
        "{%0,%1,%2,%3}, {%4,%5,%6,%7}, {%8,%9}, {%0,%1,%2,%3};"
        : "+f"(d[0]), "+f"(d[1]), "+f"(d[2]), "+f"(d[3])
        : "r"(a[0]), "r"(a[1]), "r"(a[2]), "r"(a[3]), "r"(b0), "r"(b1));
}

// ---------------- k_tq: Qt[b,j,h] = tf32(Q[b,h,j]) ----------------
__global__ void k_tq(const float* __restrict__ Q) {
    __shared__ float t[32][33];
    int b = blockIdx.z;
    int j0 = blockIdx.x * 32, h0 = blockIdx.y * 32;
    int tx = threadIdx.x, ty = threadIdx.y;
    const float* qb = Q + (size_t)b * Hn * LQn;
#pragma unroll
    for (int r = 0; r < 32; r += 8)
        t[ty + r][tx] = qb[(size_t)(h0 + ty + r) * LQn + j0 + tx];
    __syncthreads();
    float* qt = g_Qt + (size_t)b * LQn * Hn;
#pragma unroll
    for (int r = 0; r < 32; r += 8)
        qt[(size_t)(j0 + ty + r) * Hn + h0 + tx] = __uint_as_float(f2tf(t[tx][ty + r]));
}

// =========================================================================
// k_S: S = cw + qw + (Ct*w3)@Qt^T via tf32 mma, hi/lo split, fp32 acc
// 128 threads / 4 warps, warp tile 64i x 64j, block 128x128, double-buffered.
// =========================================================================
#define SSTR 136
#define S_CH 2176
#define S_STAGE (4 * S_CH)
#define S_SMEM_BYTES (2 * S_STAGE * 4)

__device__ __forceinline__ void s_ldg(const float* cb, const float* qb,
                                      const float* lp, int c, int i0, int j0,
                                      int tid, float4* pc, float4* pq,
                                      float* pw1, float* pw2, float* pw3) {
    int h0 = c * 16;
#pragma unroll
    for (int t = 0; t < 4; t++) {
        int l = tid + 128 * t;
        int row = l >> 5, q = l & 31;
        pw1[t] = __ldg(&lp[h0 + row]);
        pw2[t] = __ldg(&lp[Hn + h0 + row]);
        pw3[t] = __ldg(&lp[2 * Hn + h0 + row]);
        pc[t] = *(const float4*)(cb + (size_t)(h0 + row) * LCn + i0 + q * 4);
        pq[t] = *(const float4*)(qb + (size_t)(h0 + row) * LQn + j0 + q * 4);
    }
}

__device__ __forceinline__ void s_sts(unsigned* stg, int tid,
                                      const float4* pc, const float4* pq,
                                      const float* pw1, const float* pw2,
                                      const float* pw3, float* cwp, float* qwp) {
    unsigned* Chi = stg;
    unsigned* Clo = Chi + S_CH;
    unsigned* Qhi = Clo + S_CH;
    unsigned* Qlo = Qhi + S_CH;
#pragma unroll
    for (int t = 0; t < 4; t++) {
        int l = tid + 128 * t;
        int row = l >> 5, q = l & 31;
        float cr[4] = {pc[t].x, pc[t].y, pc[t].z, pc[t].w};
        float qr[4] = {pq[t].x, pq[t].y, pq[t].z, pq[t].w};
        float w3 = pw3[t];
        uint4 ch, cl, qh, ql;
        unsigned* chp = (unsigned*)&ch;
        unsigned* clp = (unsigned*)&cl;
        unsigned* qhp = (unsigned*)&qh;
        unsigned* qlp = (unsigned*)&ql;
#pragma unroll
        for (int e = 0; e < 4; e++) {
            cwp[e] += pw1[t] * cr[e];
            qwp[e] += pw2[t] * qr[e];
            float ca = cr[e] * w3;
            unsigned hb = f2tf(ca);
            chp[e] = hb;
            clp[e] = f2tf(ca - __uint_as_float(hb));
            unsigned qhb = f2tf(qr[e]);
            qhp[e] = qhb;
            qlp[e] = f2tf(qr[e] - __uint_as_float(qhb));
        }
        int off = row * SSTR + q * 4;
        *(uint4*)&Chi[off] = ch;
        *(uint4*)&Clo[off] = cl;
        *(uint4*)&Qhi[off] = qh;
        *(uint4*)&Qlo[off] = ql;
    }
}

__global__ void __launch_bounds__(128, 2) k_S(const float* __restrict__ C,
                                              const float* __restrict__ Q,
                                              const float* __restrict__ lp) {
    extern __shared__ unsigned smu[];
    __shared__ float RedC[512];
    __shared__ float RedQ[512];
    __shared__ float cwS[128];
    __shared__ float qwS[128];

    int b = blockIdx.z;
    int j0 = blockIdx.x * 128, i0 = blockIdx.y * 128;
    int tid = threadIdx.x;
    int warp = tid >> 5, lane = tid & 31;
    int wi = warp >> 1, wj = warp & 1;
    int gid = lane >> 2, tig = lane & 3;

    const float* cb = C + (size_t)b * Hn * LCn;
    const float* qb = Q + (size_t)b * Hn * LQn;

    float acc[4][8][4];
#pragma unroll
    for (int mt = 0; mt < 4; mt++)
#pragma unroll
        for (int nt = 0; nt < 8; nt++)
#pragma unroll
            for (int r = 0; r < 4; r++) acc[mt][nt][r] = 0.f;
    float cwp[4] = {0.f, 0.f, 0.f, 0.f};
    float qwp[4] = {0.f, 0.f, 0.f, 0.f};

    float4 pc[4], pq[4];
    float pw1[4], pw2[4], pw3[4];

    s_ldg(cb, qb, lp, 0, i0, j0, tid, pc, pq, pw1, pw2, pw3);
    s_sts(smu, tid, pc, pq, pw1, pw2, pw3, cwp, qwp);
    __syncthreads();

    for (int c = 0; c < 16; c++) {
        int st = c & 1;
        if (c < 15) s_ldg(cb, qb, lp, c + 1, i0, j0, tid, pc, pq, pw1, pw2, pw3);

        unsigned* Chi = smu + st * S_STAGE;
        unsigned* Clo = Chi + S_CH;
        unsigned* Qhi = Clo + S_CH;
        unsigned* Qlo = Qhi + S_CH;
#pragma unroll
        for (int ks = 0; ks < 16; ks += 8) {
            int r0 = (ks + tig) * SSTR, r1 = (ks + tig + 4) * SSTR;
            unsigned ah[4][4], al[4][4];
#pragma unroll
            for (int mt = 0; mt < 4; mt++) {
                int col = wi * 64 + mt * 16 + gid;
                ah[mt][0] = Chi[r0 + col]; ah[mt][1] = Chi[r0 + col + 8];
                ah[mt][2] = Chi[r1 + col]; ah[mt][3] = Chi[r1 + col + 8];
                al[mt][0] = Clo[r0 + col]; al[mt][1] = Clo[r0 + col + 8];
                al[mt][2] = Clo[r1 + col]; al[mt][3] = Clo[r1 + col + 8];
            }
#pragma unroll
            for (int nt = 0; nt < 8; nt++) {
                int jj = wj * 64 + nt * 8 + gid;
                unsigned bh0 = Qhi[r0 + jj], bh1 = Qhi[r1 + jj];
                unsigned bl0 = Qlo[r0 + jj], bl1 = Qlo[r1 + jj];
#pragma unroll
                for (int mt = 0; mt < 4; mt++) {
                    mma8(acc[mt][nt], ah[mt], bh0, bh1);
                    mma8(acc[mt][nt], ah[mt], bl0, bl1);
                    mma8(acc[mt][nt], al[mt], bh0, bh1);
                }
            }
        }
        if (c < 15) s_sts(smu + (st ^ 1) * S_STAGE, tid, pc, pq, pw1, pw2, pw3, cwp, qwp);
        __syncthreads();
    }

    // reduce cw/qw partials
#pragma unroll
    for (int e = 0; e < 4; e++) {
        RedC[tid * 4 + e] = cwp[e];
        RedQ[tid * 4 + e] = qwp[e];
    }
    __syncthreads();
    {
        int q = tid >> 2, e = tid & 3;
        cwS[tid] = RedC[q * 4 + e] + RedC[(q + 32) * 4 + e]
                 + RedC[(q + 64) * 4 + e] + RedC[(q + 96) * 4 + e];
        qwS[tid] = RedQ[q * 4 + e] + RedQ[(q + 32) * 4 + e]
                 + RedQ[(q + 64) * 4 + e] + RedQ[(q + 96) * 4 + e];
    }
    __syncthreads();

    // epilogue
#pragma unroll
    for (int mt = 0; mt < 4; mt++) {
        int rl = wi * 64 + mt * 16 + gid;
        float cw0 = cwS[rl];
        float cw1 = cwS[rl + 8];
        float* s0 = &g_S[((size_t)b * LCn + i0 + rl) * LQn + j0 + wj * 64 + 2 * tig];
        float* s1 = &g_S[((size_t)b * LCn + i0 + rl + 8) * LQn + j0 + wj * 64 + 2 * tig];
#pragma unroll
        for (int nt = 0; nt < 8; nt++) {
            int jb = wj * 64 + nt * 8 + 2 * tig;
            float qx = qwS[jb], qy = qwS[jb + 1];
            *(float2*)(s0 + nt * 8) = make_float2(acc[mt][nt][0] + cw0 + qx,
                                                  acc[mt][nt][1] + cw0 + qy);
            *(float2*)(s1 + nt * 8) = make_float2(acc[mt][nt][2] + cw1 + qx,
                                                  acc[mt][nt][3] + cw1 + qy);
        }
    }
}

// =========================================================================
// k_T: T[j,h] = tf32( (1/d[j]) * sum_i exp(mask(S[i,j])) * C[h,i] )
// =========================================================================
#define TPSTR 136
#define TCH (16 * TPSTR)
#define TCSTR 20
#define TCCH (128 * TCSTR)

__device__ __forceinline__ void t_ldg(const float* Sb, const float* cmb,
                                      const float* cb, int c, int j0, int h0,
                                      int tid, float4* ps, float* pm, float4* pcv) {
#pragma unroll
    for (int t = 0; t < 2; t++) {
        int l = tid + 256 * t;
        int row = l >> 5, q = l & 31;
        ps[t] = *(const float4*)&Sb[(size_t)(c * 16 + row) * LQn + j0 + q * 4];
        pm[t] = __ldg(&cmb[c * 16 + row]);
        int hrow = l >> 2, hq = l & 3;
        pcv[t] = *(const float4*)(cb + (size_t)(h0 + hrow) * LCn + c * 16 + hq * 4);
    }
}

__device__ __forceinline__ void t_sts(unsigned* PaS, unsigned* CbS, int tid,
                                      const float4* ps, const float* pm,
                                      const float4* pcv, float* csum) {
#pragma unroll
    for (int t = 0; t < 2; t++) {
        int l = tid + 256 * t;
        int row = l >> 5, q = l & 31;
        float cm = pm[t];
        float om = 1.f - cm, mn = cm * NEGV;
        float e0 = __expf(ps[t].x * om + mn);
        float e1 = __expf(ps[t].y * om + mn);
        float e2 = __expf(ps[t].z * om + mn);
        float e3 = __expf(ps[t].w * om + mn);
        csum[0] += e0; csum[1] += e1; csum[2] += e2; csum[3] += e3;
        uint4 pv;
        pv.x = f2tf(e0); pv.y = f2tf(e1); pv.z = f2tf(e2); pv.w = f2tf(e3);
        *(uint4*)&PaS[row * TPSTR + q * 4] = pv;
        int hrow = l >> 2, hq = l & 3;
        uint4 cv;
        cv.x = f2tf(pcv[t].x); cv.y = f2tf(pcv[t].y);
        cv.z = f2tf(pcv[t].z); cv.w = f2tf(pcv[t].w);
        *(uint4*)&CbS[hrow * TCSTR + hq * 4] = cv;
    }
}

__global__ void __launch_bounds__(256, 2) k_T(const float* __restrict__ C,
                                              const float* __restrict__ cmask) {
    __shared__ unsigned Pa[2 * TCH];
    __shared__ unsigned Cb[2 * TCCH];
    __shared__ float Red[8 * 132 + 128];
    float* Inv = Red + 8 * 132;

    int b = blockIdx.z;
    int j0 = blockIdx.x * 128, h0 = blockIdx.y * 128;
    int tid = threadIdx.x;
    int warp = tid >> 5, lane = tid & 31;
    int wm = warp >> 1, wn = warp & 1;
    int gid = lane >> 2, tig = lane & 3;
    int q = tid & 31;

    float acc[2][8][4];
#pragma unroll
    for (int mt = 0; mt < 2; mt++)
#pragma unroll
        for (int nt = 0; nt < 8; nt++)
#pragma unroll
            for (int r = 0; r < 4; r++) acc[mt][nt][r] = 0.f;
    float csum[4] = {0.f, 0.f, 0.f, 0.f};

    const float* cb  = C + (size_t)b * Hn * LCn;
    const float* Sb  = g_S + (size_t)b * LCn * LQn;
    const float* cmb = cmask + b * LCn;

    float4 ps[2], pcv[2];
    float pm[2];

    t_ldg(Sb, cmb, cb, 0, j0, h0, tid, ps, pm, pcv);
    t_sts(Pa, Cb, tid, ps, pm, pcv, csum);
    __syncthreads();

    for (int c = 0; c < 128; c++) {
        int st = c & 1;
        if (c < 127) t_ldg(Sb, cmb, cb, c + 1, j0, h0, tid, ps, pm, pcv);

        unsigned* PaS = Pa + st * TCH;
        unsigned* CbS = Cb + st * TCCH;
#pragma unroll
        for (int ks = 0; ks < 16; ks += 8) {
            int r0 = (ks + tig) * TPSTR, r1 = (ks + tig + 4) * TPSTR;
            unsigned af[2][4];
#pragma unroll
            for (int mt = 0; mt < 2; mt++) {
                int col = wm * 32 + mt * 16 + gid;
                af[mt][0] = PaS[r0 + col]; af[mt][1] = PaS[r0 + col + 8];
                af[mt][2] = PaS[r1 + col]; af[mt][3] = PaS[r1 + col + 8];
            }
#pragma unroll
            for (int nt = 0; nt < 8; nt++) {
                int hh = wn * 64 + nt * 8 + gid;
                unsigned b0 = CbS[hh * TCSTR + ks + tig];
                unsigned b1 = CbS[hh * TCSTR + ks + tig + 4];
#pragma unroll
                for (int mt = 0; mt < 2; mt++) mma8(acc[mt][nt], af[mt], b0, b1);
            }
        }
        if (c < 127) t_sts(Pa + (st ^ 1) * TCH, Cb + (st ^ 1) * TCCH, tid, ps, pm, pcv, csum);
        __syncthreads();
    }

    *(float4*)&Red[warp * 132 + q * 4] = make_float4(csum[0], csum[1], csum[2], csum[3]);
    __syncthreads();
    if (tid < 128) {
        float d = 0.f;
#pragma unroll
        for (int w = 0; w < 8; w++) d += Red[w * 132 + tid];
        Inv[tid] = 1.f / d;
    }
    __syncthreads();

#pragma unroll
    for (int mt = 0; mt < 2; mt++) {
        int jl = wm * 32 + mt * 16 + gid;
        float i0v = Inv[jl];
        float i1v = Inv[jl + 8];
#pragma unroll
        for (int nt = 0; nt < 8; nt++) {
            int h = wn * 64 + nt * 8 + 2 * tig;
            float* tp = g_T + ((size_t)b * LQn + j0 + jl) * Hn + h0 + h;
            *(float2*)tp = make_float2(__uint_as_float(f2tf(acc[mt][nt][0] * i0v)),
                                       __uint_as_float(f2tf(acc[mt][nt][1] * i0v)));
            *(float2*)(tp + 8 * Hn) = make_float2(__uint_as_float(f2tf(acc[mt][nt][2] * i1v)),
                                                  __uint_as_float(f2tf(acc[mt][nt][3] * i1v)));
        }
    }
}

// =========================================================================
// k_out: 256 threads / 8 warps (2i x 4h), block 64i x 128h, warp tile 32i x 32h.
// Register softmax direct from global; pre-rounded tf32 Qt/T staged as raw
// uint4; double-buffered 16-k chunks. 2 blocks/SM (16 warps).
// =========================================================================
#define PSTR  260
#define QSTR  136
#define OCH   (16 * QSTR)
#define O_SMEM_WORDS (64 * PSTR + 4 * OCH + 256)
#define O_SMEM_BYTES (O_SMEM_WORDS * 4)

__device__ __forceinline__ void o_ldg(const unsigned* qtU, const unsigned* tU,
                                      int c, int h0, int tid, uint4* pq, uint4* pt) {
#pragma unroll
    for (int t = 0; t < 2; t++) {
        int l = tid + 256 * t;
        int row = l >> 5, q = l & 31;
        pq[t] = *(const uint4*)&qtU[(size_t)(c * 16 + row) * Hn + h0 + q * 4];
        pt[t] = *(const uint4*)&tU [(size_t)(c * 16 + row) * Hn + h0 + q * 4];
    }
}

__device__ __forceinline__ void o_sts(unsigned* Qc, unsigned* Tc, int tid,
                                      const uint4* pq, const uint4* pt) {
#pragma unroll
    for (int t = 0; t < 2; t++) {
        int l = tid + 256 * t;
        int row = l >> 5, q = l & 31;
        *(uint4*)&Qc[row * QSTR + q * 4] = pq[t];
        *(uint4*)&Tc[row * QSTR + q * 4] = pt[t];
    }
}

__global__ void __launch_bounds__(256, 2) k_out(const float* __restrict__ C,
                                                const float* __restrict__ qmask,
                                                float* __restrict__ out) {
    extern __shared__ float sm[];
    unsigned* Pau = (unsigned*)sm;                    // [64][PSTR] tf32 probs
    unsigned* stg = (unsigned*)(sm + 64 * PSTR);      // 2 stages x (Qc|Tc)
    float*    qmS = sm + 64 * PSTR + 4 * OCH;         // [256]
    float*    Ast = sm;                               // epilogue [128][36]
    float*    Bst = sm + 128 * 36;

    int b = blockIdx.z;
    int i0 = blockIdx.x * 64;
    int h0 = blockIdx.y * 128;
    int tid = threadIdx.x;
    int warp = tid >> 5, lane = tid & 31;
    int gid = lane >> 2, tig = lane & 3;
    int wm = warp >> 2, wh = warp & 3;

    // phase 0: qmask to smem
    qmS[tid] = qmask[b * LQn + tid];
    __syncthreads();

    // phase 1+2: register softmax; warp w owns rows 8w..8w+7
#pragma unroll
    for (int rr = 0; rr < 8; rr++) {
        int row = warp * 8 + rr;
        const float* sp = &g_S[((size_t)b * LCn + i0 + row) * LQn];
        float4 v0 = *(const float4*)(sp + 4 * lane);
        float4 v1 = *(const float4*)(sp + 128 + 4 * lane);
        float4 q0 = *(const float4*)&qmS[4 * lane];
        float4 q1 = *(const float4*)&qmS[128 + 4 * lane];
        float pv[8];
        pv[0] = v0.x * (1.f - q0.x) + q0.x * NEGV;
        pv[1] = v0.y * (1.f - q0.y) + q0.y * NEGV;
        pv[2] = v0.z * (1.f - q0.z) + q0.z * NEGV;
        pv[3] = v0.w * (1.f - q0.w) + q0.w * NEGV;
        pv[4] = v1.x * (1.f - q1.x) + q1.x * NEGV;
        pv[5] = v1.y * (1.f - q1.y) + q1.y * NEGV;
        pv[6] = v1.z * (1.f - q1.z) + q1.z * NEGV;
        pv[7] = v1.w * (1.f - q1.w) + q1.w * NEGV;
        float m = NINF;
#pragma unroll
        for (int c = 0; c < 8; c++) m = fmaxf(m, pv[c]);
#pragma unroll
        for (int o = 16; o > 0; o >>= 1) m = fmaxf(m, __shfl_xor_sync(0xffffffffu, m, o));
        float s = 0.f;
#pragma unroll
        for (int c = 0; c < 8; c++) {
            float e = __expf(pv[c] - m);
            pv[c] = e;
            s += e;
        }
#pragma unroll
        for (int o = 16; o > 0; o >>= 1) s += __shfl_xor_sync(0xffffffffu, s, o);
        float inv = 1.f / s;
        uint4 w0, w1;
        w0.x = f2tf(pv[0] * inv); w0.y = f2tf(pv[1] * inv);
        w0.z = f2tf(pv[2] * inv); w0.w = f2tf(pv[3] * inv);
        w1.x = f2tf(pv[4] * inv); w1.y = f2tf(pv[5] * inv);
        w1.z = f2tf(pv[6] * inv); w1.w = f2tf(pv[7] * inv);
        *(uint4*)&Pau[row * PSTR + 4 * lane] = w0;
        *(uint4*)&Pau[row * PSTR + 128 + 4 * lane] = w1;
    }
    __syncthreads();

    // phase 3: pipelined GEMMs (A = P@Qt, B = P@T) over 16-k chunks
    const unsigned* qtU = (const unsigned*)(g_Qt + (size_t)b * LQn * Hn);
    const unsigned* tU  = (const unsigned*)(g_T  + (size_t)b * LQn * Hn);

    float accA[2][4][4], accB[2][4][4];
#pragma unroll
    for (int mt = 0; mt < 2; mt++)
#pragma unroll
        for (int nt = 0; nt < 4; nt++)
#pragma unroll
            for (int r = 0; r < 4; r++) { accA[mt][nt][r] = 0.f; accB[mt][nt][r] = 0.f; }

    uint4 pq[2], pt[2];
    o_ldg(qtU, tU, 0, h0, tid, pq, pt);
    o_sts(stg, stg + OCH, tid, pq, pt);
    __syncthreads();

    for (int c = 0; c < 16; c++) {
        int st = c & 1;
        if (c < 15) o_ldg(qtU, tU, c + 1, h0, tid, pq, pt);

        unsigned* Qc = stg + st * 2 * OCH;
        unsigned* Tc = Qc + OCH;
#pragma unroll
        for (int ks = 0; ks < 2; ks++) {
            int kg = c * 16 + ks * 8;
            unsigned af[2][4];
#pragma unroll
            for (int mt = 0; mt < 2; mt++) {
                int r0 = (wm * 32 + mt * 16 + gid) * PSTR;
                int r1 = (wm * 32 + mt * 16 + gid + 8) * PSTR;
                af[mt][0] = Pau[r0 + kg + tig];
                af[mt][1] = Pau[r1 + kg + tig];
                af[mt][2] = Pau[r0 + kg + tig + 4];
                af[mt][3] = Pau[r1 + kg + tig + 4];
            }
            int r0 = (ks * 8 + tig) * QSTR, r1 = (ks * 8 + tig + 4) * QSTR;
#pragma unroll
            for (int nt = 0; nt < 4; nt++) {
                int hh = wh * 32 + nt * 8 + gid;
                unsigned qb0 = Qc[r0 + hh], qb1 = Qc[r1 + hh];
                unsigned tb0 = Tc[r0 + hh], tb1 = Tc[r1 + hh];
#pragma unroll
                for (int mt = 0; mt < 2; mt++) {
                    mma8(accA[mt][nt], af[mt], qb0, qb1);
                    mma8(accB[mt][nt], af[mt], tb0, tb1);
                }
            }
        }
        if (c < 15) o_sts(stg + (st ^ 1) * 2 * OCH, stg + (st ^ 1) * 2 * OCH + OCH, tid, pq, pt);
        __syncthreads();
    }

    // epilogue: two 32-row i-segments, staged then coalesced-written
    const size_t sec = (size_t)Hn * LCn;
    for (int seg = 0; seg < 2; seg++) {
        if (seg) __syncthreads();
        if (wm == seg) {
#pragma unroll
            for (int mt = 0; mt < 2; mt++)
#pragma unroll
                for (int nt = 0; nt < 4; nt++) {
                    int il = mt * 16 + gid;
                    int h = wh * 32 + nt * 8 + 2 * tig;
                    Ast[h * 36 + il]           = accA[mt][nt][0];
                    Ast[(h + 1) * 36 + il]     = accA[mt][nt][1];
                    Ast[h * 36 + il + 8]       = accA[mt][nt][2];
                    Ast[(h + 1) * 36 + il + 8] = accA[mt][nt][3];
                    Bst[h * 36 + il]           = accB[mt][nt][0];
                    Bst[(h + 1) * 36 + il]     = accB[mt][nt][1];
                    Bst[h * 36 + il + 8]       = accB[mt][nt][2];
                    Bst[(h + 1) * 36 + il + 8] = accB[mt][nt][3];
                }
        }
        __syncthreads();
        int hq = tid >> 3, iq = tid & 7;
#pragma unroll
        for (int hb = 0; hb < 4; hb++) {
            int h = hb * 32 + hq;
            float4 a  = *(float4*)&Ast[h * 36 + 4 * iq];
            float4 bt = *(float4*)&Bst[h * 36 + 4 * iq];
            const float* cp = C + ((size_t)b * Hn + h0 + h) * LCn + i0 + seg * 32 + 4 * iq;
            float4 cv = *(const float4*)cp;
            float4 ca  = make_float4(cv.x * a.x, cv.y * a.y, cv.z * a.z, cv.w * a.w);
            float4 cb2 = make_float4(cv.x * bt.x, cv.y * bt.y, cv.z * bt.z, cv.w * bt.w);
            float* ob = out + ((size_t)b * 4 * Hn + h0 + h) * LCn + i0 + seg * 32 + 4 * iq;
            *(float4*)(ob)           = cv;
            *(float4*)(ob + sec)     = a;
            *(float4*)(ob + 2 * sec) = ca;
            *(float4*)(ob + 3 * sec) = cb2;
        }
    }
}

// ---------------- launch ----------------
extern "C" void kernel_launch(void* const* d_in, const int* in_sizes, int n_in,
                              void* d_out, int out_size) {
    const float* C     = (const float*)d_in[0];
    const float* Q     = (const float*)d_in[1];
    const float* cmask = (const float*)d_in[2];
    const float* qmask = (const float*)d_in[3];
    const float* lp    = (const float*)d_in[4];
    float* out = (float*)d_out;

    cudaFuncSetAttribute(k_S, cudaFuncAttributeMaxDynamicSharedMemorySize, S_SMEM_BYTES);
    cudaFuncSetAttribute(k_out, cudaFuncAttributeMaxDynamicSharedMemorySize, O_SMEM_BYTES);

    k_tq<<<dim3(LQn / 32, Hn / 32, Bn), dim3(32, 8)>>>(Q);
    k_S<<<dim3(LQn / 128, LCn / 128, Bn), 128, S_SMEM_BYTES>>>(C, Q, lp);
    k_T<<<dim3(LQn / 128, Hn / 128, Bn), 256>>>(C, cmask);
    k_out<<<dim3(LCn / 64, 2, Bn), 256, O_SMEM_BYTES>>>(C, qmask, out);   // 4th -> profiled
}

// round 16
// speedup vs baseline: 1.4651x; 1.4651x over previous
#include <cuda_runtime.h>
#include <cstdint>

#define Bn  64
#define Hn  256
#define LCn 2048
#define LQn 256
#define NEGV (-1e30f)
#define NINF __int_as_float(0xff800000)

// ---------------- scratch ----------------
__device__ float g_S [(size_t)Bn * LCn * LQn];
__device__ float g_Qt[(size_t)Bn * LQn * Hn];   // tf32 bits (pre-rounded)
__device__ float g_T [(size_t)Bn * LQn * Hn];   // tf32 bits (pre-rounded)

// ---------------- helpers ----------------
__device__ __forceinline__ unsigned f2tf(float x) {
    unsigned r; asm("cvt.rna.tf32.f32 %0, %1;" : "=r"(r) : "f"(x)); return r;
}
__device__ __forceinline__ void mma8(float* d, const unsigned* a, unsigned b0, unsigned b1) {
    asm("mma.sync.aligned.m16n8k8.row.col.f32.tf32.tf32.f32 "
        "{%0,%1,%2,%3}, {%4,%5,%6,%7}, {%8,%9}, {%0,%1,%2,%3};"
        : "+f"(d[0]), "+f"(d[1]), "+f"(d[2]), "+f"(d[3])
        : "r"(a[0]), "r"(a[1]), "r"(a[2]), "r"(a[3]), "r"(b0), "r"(b1));
}

// ---------------- k_tq: Qt[b,j,h] = tf32(Q[b,h,j]) ----------------
__global__ void k_tq(const float* __restrict__ Q) {
    __shared__ float t[32][33];
    int b = blockIdx.z;
    int j0 = blockIdx.x * 32, h0 = blockIdx.y * 32;
    int tx = threadIdx.x, ty = threadIdx.y;
    const float* qb = Q + (size_t)b * Hn * LQn;
#pragma unroll
    for (int r = 0; r < 32; r += 8)
        t[ty + r][tx] = qb[(size_t)(h0 + ty + r) * LQn + j0 + tx];
    __syncthreads();
    float* qt = g_Qt + (size_t)b * LQn * Hn;
#pragma unroll
    for (int r = 0; r < 32; r += 8)
        qt[(size_t)(j0 + ty + r) * Hn + h0 + tx] = __uint_as_float(f2tf(t[tx][ty + r]));
}

// =========================================================================
// k_S: S = cw + qw + (Ct*w3)@Qt^T via tf32 mma, hi/lo split, fp32 acc
// 128 threads / 4 warps, warp tile 64i x 64j, block 128x128, double-buffered.
// =========================================================================
#define SSTR 136
#define S_CH 2176
#define S_STAGE (4 * S_CH)
#define S_SMEM_BYTES (2 * S_STAGE * 4)

__device__ __forceinline__ void s_ldg(const float* cb, const float* qb,
                                      const float* lp, int c, int i0, int j0,
                                      int tid, float4* pc, float4* pq,
                                      float* pw1, float* pw2, float* pw3) {
    int h0 = c * 16;
#pragma unroll
    for (int t = 0; t < 4; t++) {
        int l = tid + 128 * t;
        int row = l >> 5, q = l & 31;
        pw1[t] = __ldg(&lp[h0 + row]);
        pw2[t] = __ldg(&lp[Hn + h0 + row]);
        pw3[t] = __ldg(&lp[2 * Hn + h0 + row]);
        pc[t] = *(const float4*)(cb + (size_t)(h0 + row) * LCn + i0 + q * 4);
        pq[t] = *(const float4*)(qb + (size_t)(h0 + row) * LQn + j0 + q * 4);
    }
}

__device__ __forceinline__ void s_sts(unsigned* stg, int tid,
                                      const float4* pc, const float4* pq,
                                      const float* pw1, const float* pw2,
                                      const float* pw3, float* cwp, float* qwp) {
    unsigned* Chi = stg;
    unsigned* Clo = Chi + S_CH;
    unsigned* Qhi = Clo + S_CH;
    unsigned* Qlo = Qhi + S_CH;
#pragma unroll
    for (int t = 0; t < 4; t++) {
        int l = tid + 128 * t;
        int row = l >> 5, q = l & 31;
        float cr[4] = {pc[t].x, pc[t].y, pc[t].z, pc[t].w};
        float qr[4] = {pq[t].x, pq[t].y, pq[t].z, pq[t].w};
        float w3 = pw3[t];
        uint4 ch, cl, qh, ql;
        unsigned* chp = (unsigned*)&ch;
        unsigned* clp = (unsigned*)&cl;
        unsigned* qhp = (unsigned*)&qh;
        unsigned* qlp = (unsigned*)&ql;
#pragma unroll
        for (int e = 0; e < 4; e++) {
            cwp[e] += pw1[t] * cr[e];
            qwp[e] += pw2[t] * qr[e];
            float ca = cr[e] * w3;
            unsigned hb = f2tf(ca);
            chp[e] = hb;
            clp[e] = f2tf(ca - __uint_as_float(hb));
            unsigned qhb = f2tf(qr[e]);
            qhp[e] = qhb;
            qlp[e] = f2tf(qr[e] - __uint_as_float(qhb));
        }
        int off = row * SSTR + q * 4;
        *(uint4*)&Chi[off] = ch;
        *(uint4*)&Clo[off] = cl;
        *(uint4*)&Qhi[off] = qh;
        *(uint4*)&Qlo[off] = ql;
    }
}

__global__ void __launch_bounds__(128, 2) k_S(const float* __restrict__ C,
                                              const float* __restrict__ Q,
                                              const float* __restrict__ lp) {
    extern __shared__ unsigned smu[];
    __shared__ float RedC[512];
    __shared__ float RedQ[512];
    __shared__ float cwS[128];
    __shared__ float qwS[128];

    int b = blockIdx.z;
    int j0 = blockIdx.x * 128, i0 = blockIdx.y * 128;
    int tid = threadIdx.x;
    int warp = tid >> 5, lane = tid & 31;
    int wi = warp >> 1, wj = warp & 1;
    int gid = lane >> 2, tig = lane & 3;

    const float* cb = C + (size_t)b * Hn * LCn;
    const float* qb = Q + (size_t)b * Hn * LQn;

    float acc[4][8][4];
#pragma unroll
    for (int mt = 0; mt < 4; mt++)
#pragma unroll
        for (int nt = 0; nt < 8; nt++)
#pragma unroll
            for (int r = 0; r < 4; r++) acc[mt][nt][r] = 0.f;
    float cwp[4] = {0.f, 0.f, 0.f, 0.f};
    float qwp[4] = {0.f, 0.f, 0.f, 0.f};

    float4 pc[4], pq[4];
    float pw1[4], pw2[4], pw3[4];

    s_ldg(cb, qb, lp, 0, i0, j0, tid, pc, pq, pw1, pw2, pw3);
    s_sts(smu, tid, pc, pq, pw1, pw2, pw3, cwp, qwp);
    __syncthreads();

    for (int c = 0; c < 16; c++) {
        int st = c & 1;
        if (c < 15) s_ldg(cb, qb, lp, c + 1, i0, j0, tid, pc, pq, pw1, pw2, pw3);

        unsigned* Chi = smu + st * S_STAGE;
        unsigned* Clo = Chi + S_CH;
        unsigned* Qhi = Clo + S_CH;
        unsigned* Qlo = Qhi + S_CH;
#pragma unroll
        for (int ks = 0; ks < 16; ks += 8) {
            int r0 = (ks + tig) * SSTR, r1 = (ks + tig + 4) * SSTR;
            unsigned ah[4][4], al[4][4];
#pragma unroll
            for (int mt = 0; mt < 4; mt++) {
                int col = wi * 64 + mt * 16 + gid;
                ah[mt][0] = Chi[r0 + col]; ah[mt][1] = Chi[r0 + col + 8];
                ah[mt][2] = Chi[r1 + col]; ah[mt][3] = Chi[r1 + col + 8];
                al[mt][0] = Clo[r0 + col]; al[mt][1] = Clo[r0 + col + 8];
                al[mt][2] = Clo[r1 + col]; al[mt][3] = Clo[r1 + col + 8];
            }
#pragma unroll
            for (int nt = 0; nt < 8; nt++) {
                int jj = wj * 64 + nt * 8 + gid;
                unsigned bh0 = Qhi[r0 + jj], bh1 = Qhi[r1 + jj];
                unsigned bl0 = Qlo[r0 + jj], bl1 = Qlo[r1 + jj];
#pragma unroll
                for (int mt = 0; mt < 4; mt++) {
                    mma8(acc[mt][nt], ah[mt], bh0, bh1);
                    mma8(acc[mt][nt], ah[mt], bl0, bl1);
                    mma8(acc[mt][nt], al[mt], bh0, bh1);
                }
            }
        }
        if (c < 15) s_sts(smu + (st ^ 1) * S_STAGE, tid, pc, pq, pw1, pw2, pw3, cwp, qwp);
        __syncthreads();
    }

    // reduce cw/qw partials
#pragma unroll
    for (int e = 0; e < 4; e++) {
        RedC[tid * 4 + e] = cwp[e];
        RedQ[tid * 4 + e] = qwp[e];
    }
    __syncthreads();
    {
        int q = tid >> 2, e = tid & 3;
        cwS[tid] = RedC[q * 4 + e] + RedC[(q + 32) * 4 + e]
                 + RedC[(q + 64) * 4 + e] + RedC[(q + 96) * 4 + e];
        qwS[tid] = RedQ[q * 4 + e] + RedQ[(q + 32) * 4 + e]
                 + RedQ[(q + 64) * 4 + e] + RedQ[(q + 96) * 4 + e];
    }
    __syncthreads();

    // epilogue
#pragma unroll
    for (int mt = 0; mt < 4; mt++) {
        int rl = wi * 64 + mt * 16 + gid;
        float cw0 = cwS[rl];
        float cw1 = cwS[rl + 8];
        float* s0 = &g_S[((size_t)b * LCn + i0 + rl) * LQn + j0 + wj * 64 + 2 * tig];
        float* s1 = &g_S[((size_t)b * LCn + i0 + rl + 8) * LQn + j0 + wj * 64 + 2 * tig];
#pragma unroll
        for (int nt = 0; nt < 8; nt++) {
            int jb = wj * 64 + nt * 8 + 2 * tig;
            float qx = qwS[jb], qy = qwS[jb + 1];
            *(float2*)(s0 + nt * 8) = make_float2(acc[mt][nt][0] + cw0 + qx,
                                                  acc[mt][nt][1] + cw0 + qy);
            *(float2*)(s1 + nt * 8) = make_float2(acc[mt][nt][2] + cw1 + qx,
                                                  acc[mt][nt][3] + cw1 + qy);
        }
    }
}

// =========================================================================
// k_T: T[j,h] = tf32( (1/d[j]) * sum_i exp(mask(S[i,j])) * C[h,i] )
// =========================================================================
#define TPSTR 136
#define TCH (16 * TPSTR)
#define TCSTR 20
#define TCCH (128 * TCSTR)

__device__ __forceinline__ void t_ldg(const float* Sb, const float* cmb,
                                      const float* cb, int c, int j0, int h0,
                                      int tid, float4* ps, float* pm, float4* pcv) {
#pragma unroll
    for (int t = 0; t < 2; t++) {
        int l = tid + 256 * t;
        int row = l >> 5, q = l & 31;
        ps[t] = *(const float4*)&Sb[(size_t)(c * 16 + row) * LQn + j0 + q * 4];
        pm[t] = __ldg(&cmb[c * 16 + row]);
        int hrow = l >> 2, hq = l & 3;
        pcv[t] = *(const float4*)(cb + (size_t)(h0 + hrow) * LCn + c * 16 + hq * 4);
    }
}

__device__ __forceinline__ void t_sts(unsigned* PaS, unsigned* CbS, int tid,
                                      const float4* ps, const float* pm,
                                      const float4* pcv, float* csum) {
#pragma unroll
    for (int t = 0; t < 2; t++) {
        int l = tid + 256 * t;
        int row = l >> 5, q = l & 31;
        float cm = pm[t];
        float om = 1.f - cm, mn = cm * NEGV;
        float e0 = __expf(ps[t].x * om + mn);
        float e1 = __expf(ps[t].y * om + mn);
        float e2 = __expf(ps[t].z * om + mn);
        float e3 = __expf(ps[t].w * om + mn);
        csum[0] += e0; csum[1] += e1; csum[2] += e2; csum[3] += e3;
        uint4 pv;
        pv.x = f2tf(e0); pv.y = f2tf(e1); pv.z = f2tf(e2); pv.w = f2tf(e3);
        *(uint4*)&PaS[row * TPSTR + q * 4] = pv;
        int hrow = l >> 2, hq = l & 3;
        uint4 cv;
        cv.x = f2tf(pcv[t].x); cv.y = f2tf(pcv[t].y);
        cv.z = f2tf(pcv[t].z); cv.w = f2tf(pcv[t].w);
        *(uint4*)&CbS[hrow * TCSTR + hq * 4] = cv;
    }
}

__global__ void __launch_bounds__(256, 2) k_T(const float* __restrict__ C,
                                              const float* __restrict__ cmask) {
    __shared__ unsigned Pa[2 * TCH];
    __shared__ unsigned Cb[2 * TCCH];
    __shared__ float Red[8 * 132 + 128];
    float* Inv = Red + 8 * 132;

    int b = blockIdx.z;
    int j0 = blockIdx.x * 128, h0 = blockIdx.y * 128;
    int tid = threadIdx.x;
    int warp = tid >> 5, lane = tid & 31;
    int wm = warp >> 1, wn = warp & 1;
    int gid = lane >> 2, tig = lane & 3;
    int q = tid & 31;

    float acc[2][8][4];
#pragma unroll
    for (int mt = 0; mt < 2; mt++)
#pragma unroll
        for (int nt = 0; nt < 8; nt++)
#pragma unroll
            for (int r = 0; r < 4; r++) acc[mt][nt][r] = 0.f;
    float csum[4] = {0.f, 0.f, 0.f, 0.f};

    const float* cb  = C + (size_t)b * Hn * LCn;
    const float* Sb  = g_S + (size_t)b * LCn * LQn;
    const float* cmb = cmask + b * LCn;

    float4 ps[2], pcv[2];
    float pm[2];

    t_ldg(Sb, cmb, cb, 0, j0, h0, tid, ps, pm, pcv);
    t_sts(Pa, Cb, tid, ps, pm, pcv, csum);
    __syncthreads();

    for (int c = 0; c < 128; c++) {
        int st = c & 1;
        if (c < 127) t_ldg(Sb, cmb, cb, c + 1, j0, h0, tid, ps, pm, pcv);

        unsigned* PaS = Pa + st * TCH;
        unsigned* CbS = Cb + st * TCCH;
#pragma unroll
        for (int ks = 0; ks < 16; ks += 8) {
            int r0 = (ks + tig) * TPSTR, r1 = (ks + tig + 4) * TPSTR;
            unsigned af[2][4];
#pragma unroll
            for (int mt = 0; mt < 2; mt++) {
                int col = wm * 32 + mt * 16 + gid;
                af[mt][0] = PaS[r0 + col]; af[mt][1] = PaS[r0 + col + 8];
                af[mt][2] = PaS[r1 + col]; af[mt][3] = PaS[r1 + col + 8];
            }
#pragma unroll
            for (int nt = 0; nt < 8; nt++) {
                int hh = wn * 64 + nt * 8 + gid;
                unsigned b0 = CbS[hh * TCSTR + ks + tig];
                unsigned b1 = CbS[hh * TCSTR + ks + tig + 4];
#pragma unroll
                for (int mt = 0; mt < 2; mt++) mma8(acc[mt][nt], af[mt], b0, b1);
            }
        }
        if (c < 127) t_sts(Pa + (st ^ 1) * TCH, Cb + (st ^ 1) * TCCH, tid, ps, pm, pcv, csum);
        __syncthreads();
    }

    *(float4*)&Red[warp * 132 + q * 4] = make_float4(csum[0], csum[1], csum[2], csum[3]);
    __syncthreads();
    if (tid < 128) {
        float d = 0.f;
#pragma unroll
        for (int w = 0; w < 8; w++) d += Red[w * 132 + tid];
        Inv[tid] = 1.f / d;
    }
    __syncthreads();

#pragma unroll
    for (int mt = 0; mt < 2; mt++) {
        int jl = wm * 32 + mt * 16 + gid;
        float i0v = Inv[jl];
        float i1v = Inv[jl + 8];
#pragma unroll
        for (int nt = 0; nt < 8; nt++) {
            int h = wn * 64 + nt * 8 + 2 * tig;
            float* tp = g_T + ((size_t)b * LQn + j0 + jl) * Hn + h0 + h;
            *(float2*)tp = make_float2(__uint_as_float(f2tf(acc[mt][nt][0] * i0v)),
                                       __uint_as_float(f2tf(acc[mt][nt][1] * i0v)));
            *(float2*)(tp + 8 * Hn) = make_float2(__uint_as_float(f2tf(acc[mt][nt][2] * i1v)),
                                                  __uint_as_float(f2tf(acc[mt][nt][3] * i1v)));
        }
    }
}

// =========================================================================
// k_out: R11 structure — 256 threads / 8 warps (2i x 4h), block 64i x 128h,
// warp tile 32i x 32h, smem-staged softmax. Changes vs R11: raw uint4
// staging of pre-rounded tf32 Qt/T (no cvt), QSTR 132->136 (conflict-free).
// =========================================================================
#define PSTR  260
#define QSTR  136
#define OCH   (16 * QSTR)
#define O_SMEM_WORDS (64 * PSTR + 4 * OCH)
#define O_SMEM_BYTES (O_SMEM_WORDS * 4)

__device__ __forceinline__ void o_ldg(const unsigned* qtU, const unsigned* tU,
                                      int c, int h0, int tid, uint4* pq, uint4* pt) {
#pragma unroll
    for (int t = 0; t < 2; t++) {
        int l = tid + 256 * t;
        int row = l >> 5, q = l & 31;
        pq[t] = *(const uint4*)&qtU[(size_t)(c * 16 + row) * Hn + h0 + q * 4];
        pt[t] = *(const uint4*)&tU [(size_t)(c * 16 + row) * Hn + h0 + q * 4];
    }
}

__device__ __forceinline__ void o_sts(unsigned* Qc, unsigned* Tc, int tid,
                                      const uint4* pq, const uint4* pt) {
#pragma unroll
    for (int t = 0; t < 2; t++) {
        int l = tid + 256 * t;
        int row = l >> 5, q = l & 31;
        *(uint4*)&Qc[row * QSTR + q * 4] = pq[t];
        *(uint4*)&Tc[row * QSTR + q * 4] = pt[t];
    }
}

__global__ void __launch_bounds__(256, 2) k_out(const float* __restrict__ C,
                                                const float* __restrict__ qmask,
                                                float* __restrict__ out) {
    extern __shared__ float sm[];
    float*    Paf = sm;                           // [64][PSTR] masked S -> tf32 probs
    unsigned* Pau = (unsigned*)sm;
    unsigned* stg = (unsigned*)(sm + 64 * PSTR);  // 2 stages x (Qc|Tc)
    float*    Ast = sm;                           // epilogue [128][36]
    float*    Bst = sm + 128 * 36;

    int b = blockIdx.z;
    int i0 = blockIdx.x * 64;
    int h0 = blockIdx.y * 128;
    int tid = threadIdx.x;
    int warp = tid >> 5, lane = tid & 31;
    int gid = lane >> 2, tig = lane & 3;
    int wm = warp >> 2, wh = warp & 3;

    // phase 1: masked S rows into smem (cooperative, coalesced)
#pragma unroll
    for (int t = 0; t < 16; t++) {
        int l = tid + 256 * t;
        int row = l >> 6, jq = l & 63;
        float4 v  = *(const float4*)&g_S[((size_t)b * LCn + i0 + row) * LQn + 4 * jq];
        float4 qm = *(const float4*)&qmask[b * LQn + 4 * jq];
        v.x = v.x * (1.f - qm.x) + qm.x * NEGV;
        v.y = v.y * (1.f - qm.y) + qm.y * NEGV;
        v.z = v.z * (1.f - qm.z) + qm.z * NEGV;
        v.w = v.w * (1.f - qm.w) + qm.w * NEGV;
        *(float4*)&Paf[row * PSTR + 4 * jq] = v;
    }
    __syncthreads();

    // phase 2: row softmax in place (warp w owns rows 8w..8w+7)
#pragma unroll
    for (int rr = 0; rr < 8; rr++) {
        int row = warp * 8 + rr;
        float pv[8], m = NINF;
#pragma unroll
        for (int cc = 0; cc < 8; cc++) {
            pv[cc] = Paf[row * PSTR + lane + 32 * cc];
            m = fmaxf(m, pv[cc]);
        }
#pragma unroll
        for (int o = 16; o > 0; o >>= 1) m = fmaxf(m, __shfl_xor_sync(0xffffffffu, m, o));
        float s = 0.f;
#pragma unroll
        for (int cc = 0; cc < 8; cc++) {
            float e = __expf(pv[cc] - m);
            pv[cc] = e;
            s += e;
        }
#pragma unroll
        for (int o = 16; o > 0; o >>= 1) s += __shfl_xor_sync(0xffffffffu, s, o);
        float inv = 1.f / s;
#pragma unroll
        for (int cc = 0; cc < 8; cc++)
            Pau[row * PSTR + lane + 32 * cc] = f2tf(pv[cc] * inv);
    }
    __syncthreads();

    // phase 3: pipelined GEMMs (A = P@Qt, B = P@T) over 16-k chunks
    const unsigned* qtU = (const unsigned*)(g_Qt + (size_t)b * LQn * Hn);
    const unsigned* tU  = (const unsigned*)(g_T  + (size_t)b * LQn * Hn);

    float accA[2][4][4], accB[2][4][4];
#pragma unroll
    for (int mt = 0; mt < 2; mt++)
#pragma unroll
        for (int nt = 0; nt < 4; nt++)
#pragma unroll
            for (int r = 0; r < 4; r++) { accA[mt][nt][r] = 0.f; accB[mt][nt][r] = 0.f; }

    uint4 pq[2], pt[2];
    o_ldg(qtU, tU, 0, h0, tid, pq, pt);
    o_sts(stg, stg + OCH, tid, pq, pt);
    __syncthreads();

    for (int c = 0; c < 16; c++) {
        int st = c & 1;
        if (c < 15) o_ldg(qtU, tU, c + 1, h0, tid, pq, pt);

        unsigned* Qc = stg + st * 2 * OCH;
        unsigned* Tc = Qc + OCH;
#pragma unroll
        for (int ks = 0; ks < 2; ks++) {
            int kg = c * 16 + ks * 8;
            unsigned af[2][4];
#pragma unroll
            for (int mt = 0; mt < 2; mt++) {
                int r0 = (wm * 32 + mt * 16 + gid) * PSTR;
                int r1 = (wm * 32 + mt * 16 + gid + 8) * PSTR;
                af[mt][0] = Pau[r0 + kg + tig];
                af[mt][1] = Pau[r1 + kg + tig];
                af[mt][2] = Pau[r0 + kg + tig + 4];
                af[mt][3] = Pau[r1 + kg + tig + 4];
            }
            int r0 = (ks * 8 + tig) * QSTR, r1 = (ks * 8 + tig + 4) * QSTR;
#pragma unroll
            for (int nt = 0; nt < 4; nt++) {
                int hh = wh * 32 + nt * 8 + gid;
                unsigned qb0 = Qc[r0 + hh], qb1 = Qc[r1 + hh];
                unsigned tb0 = Tc[r0 + hh], tb1 = Tc[r1 + hh];
#pragma unroll
                for (int mt = 0; mt < 2; mt++) {
                    mma8(accA[mt][nt], af[mt], qb0, qb1);
                    mma8(accB[mt][nt], af[mt], tb0, tb1);
                }
            }
        }
        if (c < 15) o_sts(stg + (st ^ 1) * 2 * OCH, stg + (st ^ 1) * 2 * OCH + OCH, tid, pq, pt);
        __syncthreads();
    }

    // epilogue: two 32-row i-segments, staged then coalesced-written
    const size_t sec = (size_t)Hn * LCn;
    for (int seg = 0; seg < 2; seg++) {
        if (seg) __syncthreads();
        if (wm == seg) {
#pragma unroll
            for (int mt = 0; mt < 2; mt++)
#pragma unroll
                for (int nt = 0; nt < 4; nt++) {
                    int il = mt * 16 + gid;
                    int h = wh * 32 + nt * 8 + 2 * tig;
                    Ast[h * 36 + il]           = accA[mt][nt][0];
                    Ast[(h + 1) * 36 + il]     = accA[mt][nt][1];
                    Ast[h * 36 + il + 8]       = accA[mt][nt][2];
                    Ast[(h + 1) * 36 + il + 8] = accA[mt][nt][3];
                    Bst[h * 36 + il]           = accB[mt][nt][0];
                    Bst[(h + 1) * 36 + il]     = accB[mt][nt][1];
                    Bst[h * 36 + il + 8]       = accB[mt][nt][2];
                    Bst[(h + 1) * 36 + il + 8] = accB[mt][nt][3];
                }
        }
        __syncthreads();
        int hq = tid >> 3, iq = tid & 7;
#pragma unroll
        for (int hb = 0; hb < 4; hb++) {
            int h = hb * 32 + hq;
            float4 a  = *(float4*)&Ast[h * 36 + 4 * iq];
            float4 bt = *(float4*)&Bst[h * 36 + 4 * iq];
            const float* cp = C + ((size_t)b * Hn + h0 + h) * LCn + i0 + seg * 32 + 4 * iq;
            float4 cv = *(const float4*)cp;
            float4 ca  = make_float4(cv.x * a.x, cv.y * a.y, cv.z * a.z, cv.w * a.w);
            float4 cb2 = make_float4(cv.x * bt.x, cv.y * bt.y, cv.z * bt.z, cv.w * bt.w);
            float* ob = out + ((size_t)b * 4 * Hn + h0 + h) * LCn + i0 + seg * 32 + 4 * iq;
            *(float4*)(ob)           = cv;
            *(float4*)(ob + sec)     = a;
            *(float4*)(ob + 2 * sec) = ca;
            *(float4*)(ob + 3 * sec) = cb2;
        }
    }
}

// ---------------- launch ----------------
extern "C" void kernel_launch(void* const* d_in, const int* in_sizes, int n_in,
                              void* d_out, int out_size) {
    const float* C     = (const float*)d_in[0];
    const float* Q     = (const float*)d_in[1];
    const float* cmask = (const float*)d_in[2];
    const float* qmask = (const float*)d_in[3];
    const float* lp    = (const float*)d_in[4];
    float* out = (float*)d_out;

    cudaFuncSetAttribute(k_S, cudaFuncAttributeMaxDynamicSharedMemorySize, S_SMEM_BYTES);
    cudaFuncSetAttribute(k_out, cudaFuncAttributeMaxDynamicSharedMemorySize, O_SMEM_BYTES);

    k_tq<<<dim3(LQn / 32, Hn / 32, Bn), dim3(32, 8)>>>(Q);
    k_S<<<dim3(LQn / 128, LCn / 128, Bn), 128, S_SMEM_BYTES>>>(C, Q, lp);
    k_T<<<dim3(LQn / 128, Hn / 128, Bn), 256>>>(C, cmask);
    k_out<<<dim3(LCn / 64, 2, Bn), 256, O_SMEM_BYTES>>>(C, qmask, out);   // 4th -> profiled
}